// round 1
// baseline (speedup 1.0000x reference)
#include <cuda_runtime.h>
#include <math.h>

#define B_ 64
#define H_ 1024

// Scratch (allocation-free rule: __device__ globals)
__device__ float g_s[9][B_ * H_];   // raw pre-activations of the 9 K=1024 GEMMs
__device__ float g_ep[8][B_ * H_];  // split-K partials of e = k_t @ We

// ----------------------------------------------------------------------------
// Kernel 1: nine K=1024 GEMMs, M=64, N=1024. TN=64 -> 16 n-tiles x 9 = 144 blocks
// mats: 0 x@Wi[:1024]  1 h@Wi[1024:]  2 x@Wf[:1024] 3 h@Wf[1024:]
//       4 x@Wo[:1024]  5 h@Wo[1024:]  6 x@Wk        7 x@Wv        8 h@Wq
// ----------------------------------------------------------------------------
__global__ __launch_bounds__(256, 1) void gemm9_kernel(
    const float* __restrict__ x, const float* __restrict__ h,
    const float* __restrict__ Wi, const float* __restrict__ Wf,
    const float* __restrict__ Wo, const float* __restrict__ Wk,
    const float* __restrict__ Wv, const float* __restrict__ Wq)
{
    constexpr int TK = 32;
    __shared__ __align__(16) float As[TK][64 + 4];
    __shared__ __align__(16) float Ws[TK][64 + 4];

    const int mat = blockIdx.y;
    const float* A;
    const float* W;
    switch (mat) {
        case 0: A = x; W = Wi;             break;
        case 1: A = h; W = Wi + H_ * H_;   break;
        case 2: A = x; W = Wf;             break;
        case 3: A = h; W = Wf + H_ * H_;   break;
        case 4: A = x; W = Wo;             break;
        case 5: A = h; W = Wo + H_ * H_;   break;
        case 6: A = x; W = Wk;             break;
        case 7: A = x; W = Wv;             break;
        default: A = h; W = Wq;            break;
    }
    float* out = g_s[mat];

    const int n0 = blockIdx.x * 64;
    const int t  = threadIdx.x;
    const int tr = t >> 4;       // 0..15 -> rows tr*4..tr*4+3
    const int tc = t & 15;       // 0..15 -> cols tc*4..tc*4+3

    float acc[4][4] = {};

    for (int k0 = 0; k0 < H_; k0 += TK) {
        // Load A tile 64x32 (transposed into As[k][m])
        int idx = t;
        #pragma unroll
        for (int p = 0; p < 2; p++, idx += 256) {
            int row = idx >> 3;
            int kq  = (idx & 7) << 2;
            float4 v = *(const float4*)(A + row * H_ + k0 + kq);
            As[kq + 0][row] = v.x;
            As[kq + 1][row] = v.y;
            As[kq + 2][row] = v.z;
            As[kq + 3][row] = v.w;
        }
        // Load W tile 32x64
        {
            int wr = t >> 4;
            int wc = (t & 15) << 2;
            #pragma unroll
            for (int p = 0; p < 2; p++) {
                float4 v = *(const float4*)(W + (size_t)(k0 + wr + p * 16) * H_ + n0 + wc);
                *(float4*)&Ws[wr + p * 16][wc] = v;
            }
        }
        __syncthreads();

        #pragma unroll
        for (int kk = 0; kk < TK; kk++) {
            float4 a = *(const float4*)&As[kk][tr << 2];
            float4 b = *(const float4*)&Ws[kk][tc << 2];
            acc[0][0] = fmaf(a.x, b.x, acc[0][0]);
            acc[0][1] = fmaf(a.x, b.y, acc[0][1]);
            acc[0][2] = fmaf(a.x, b.z, acc[0][2]);
            acc[0][3] = fmaf(a.x, b.w, acc[0][3]);
            acc[1][0] = fmaf(a.y, b.x, acc[1][0]);
            acc[1][1] = fmaf(a.y, b.y, acc[1][1]);
            acc[1][2] = fmaf(a.y, b.z, acc[1][2]);
            acc[1][3] = fmaf(a.y, b.w, acc[1][3]);
            acc[2][0] = fmaf(a.z, b.x, acc[2][0]);
            acc[2][1] = fmaf(a.z, b.y, acc[2][1]);
            acc[2][2] = fmaf(a.z, b.z, acc[2][2]);
            acc[2][3] = fmaf(a.z, b.w, acc[2][3]);
            acc[3][0] = fmaf(a.w, b.x, acc[3][0]);
            acc[3][1] = fmaf(a.w, b.y, acc[3][1]);
            acc[3][2] = fmaf(a.w, b.z, acc[3][2]);
            acc[3][3] = fmaf(a.w, b.w, acc[3][3]);
        }
        __syncthreads();
    }

    #pragma unroll
    for (int i = 0; i < 4; i++) {
        int row = (tr << 2) + i;
        float4 v = make_float4(acc[i][0], acc[i][1], acc[i][2], acc[i][3]);
        *(float4*)(out + row * H_ + n0 + (tc << 2)) = v;
    }
}

// ----------------------------------------------------------------------------
// Kernel 2: e partials. A = (g_s[6] + bk) [64,1024], W = We. split-K=8.
// grid (16 n-tiles, 8 k-chunks of 128)
// ----------------------------------------------------------------------------
__global__ __launch_bounds__(256, 1) void egemm_kernel(
    const float* __restrict__ We, const float* __restrict__ bk)
{
    constexpr int TK = 32;
    __shared__ __align__(16) float As[TK][64 + 4];
    __shared__ __align__(16) float Ws[TK][64 + 4];

    const float* A = &g_s[6][0];
    float* out = &g_ep[blockIdx.y][0];
    const int kbase = blockIdx.y * 128;
    const int n0 = blockIdx.x * 64;
    const int t  = threadIdx.x;
    const int tr = t >> 4;
    const int tc = t & 15;

    float acc[4][4] = {};

    for (int k0 = kbase; k0 < kbase + 128; k0 += TK) {
        int idx = t;
        #pragma unroll
        for (int p = 0; p < 2; p++, idx += 256) {
            int row = idx >> 3;
            int kq  = (idx & 7) << 2;
            float4 v  = *(const float4*)(A + row * H_ + k0 + kq);
            float4 bv = *(const float4*)(bk + k0 + kq);
            As[kq + 0][row] = v.x + bv.x;
            As[kq + 1][row] = v.y + bv.y;
            As[kq + 2][row] = v.z + bv.z;
            As[kq + 3][row] = v.w + bv.w;
        }
        {
            int wr = t >> 4;
            int wc = (t & 15) << 2;
            #pragma unroll
            for (int p = 0; p < 2; p++) {
                float4 v = *(const float4*)(We + (size_t)(k0 + wr + p * 16) * H_ + n0 + wc);
                *(float4*)&Ws[wr + p * 16][wc] = v;
            }
        }
        __syncthreads();

        #pragma unroll
        for (int kk = 0; kk < TK; kk++) {
            float4 a = *(const float4*)&As[kk][tr << 2];
            float4 b = *(const float4*)&Ws[kk][tc << 2];
            #pragma unroll
            for (int i = 0; i < 4; i++) {
                float av = (i == 0) ? a.x : (i == 1) ? a.y : (i == 2) ? a.z : a.w;
                acc[i][0] = fmaf(av, b.x, acc[i][0]);
                acc[i][1] = fmaf(av, b.y, acc[i][1]);
                acc[i][2] = fmaf(av, b.z, acc[i][2]);
                acc[i][3] = fmaf(av, b.w, acc[i][3]);
            }
        }
        __syncthreads();
    }

    #pragma unroll
    for (int i = 0; i < 4; i++) {
        int row = (tr << 2) + i;
        float4 v = make_float4(acc[i][0], acc[i][1], acc[i][2], acc[i][3]);
        *(float4*)(out + row * H_ + n0 + (tc << 2)) = v;
    }
}

// ----------------------------------------------------------------------------
// Kernel 3: the roofline pass. Streams C_prev -> C_t once, fused with gates,
// h numerator dot, n_t, h_t. One warp per C row; grid (128 row-groups, 64 b).
// ----------------------------------------------------------------------------
__device__ __forceinline__ float sigmoidf_(float z) {
    return 1.0f / (1.0f + expf(-z));
}

__global__ __launch_bounds__(256, 8) void update_kernel(
    const float* __restrict__ C_prev, const float* __restrict__ n_prev,
    const float* __restrict__ bi, const float* __restrict__ bf,
    const float* __restrict__ bo, const float* __restrict__ bk,
    const float* __restrict__ bv, const float* __restrict__ bq,
    const float* __restrict__ be,
    float* __restrict__ out_h, float* __restrict__ out_C,
    float* __restrict__ out_n)
{
    __shared__ __align__(16) float ks[H_];
    __shared__ __align__(16) float qs[H_];

    const int b    = blockIdx.y;
    const int r0   = blockIdx.x * 8;
    const int t    = threadIdx.x;
    const int w    = t >> 5;
    const int lane = t & 31;

    // k_t[b,:] and q_t[b,:] into smem (256 threads * float4 = 1024)
    {
        int c = t << 2;
        float4 kvv = *(const float4*)(&g_s[6][b * H_] + c);
        float4 bkv = *(const float4*)(bk + c);
        float4 qvv = *(const float4*)(&g_s[8][b * H_] + c);
        float4 bqv = *(const float4*)(bq + c);
        *(float4*)&ks[c] = make_float4(kvv.x + bkv.x, kvv.y + bkv.y,
                                       kvv.z + bkv.z, kvv.w + bkv.w);
        *(float4*)&qs[c] = make_float4(qvv.x + bqv.x, qvv.y + bqv.y,
                                       qvv.z + bqv.z, qvv.w + bqv.w);
    }
    __syncthreads();

    const int r = r0 + w;
    const int br = b * H_ + r;

    const float it = sigmoidf_(g_s[0][br] + g_s[1][br] + bi[r]);
    const float ft = sigmoidf_(g_s[2][br] + g_s[3][br] + bf[r]);
    const float ot = sigmoidf_(g_s[4][br] + g_s[5][br] + bo[r]);
    const float vt = g_s[7][br] + bv[r];
    const float iv = it * vt;

    const size_t base = (size_t)b * H_ * H_ + (size_t)r * H_;
    float dot = 0.0f;

    #pragma unroll
    for (int it8 = 0; it8 < 8; it8++) {
        int c = (lane << 2) + (it8 << 7);
        float4 cp = *(const float4*)(C_prev + base + c);
        float4 kv = *(const float4*)&ks[c];
        float4 qv = *(const float4*)&qs[c];
        float4 ct;
        ct.x = fmaf(ft, cp.x, iv * kv.x);
        ct.y = fmaf(ft, cp.y, iv * kv.y);
        ct.z = fmaf(ft, cp.z, iv * kv.z);
        ct.w = fmaf(ft, cp.w, iv * kv.w);
        *(float4*)(out_C + base + c) = ct;
        dot = fmaf(ct.x, qv.x, dot);
        dot = fmaf(ct.y, qv.y, dot);
        dot = fmaf(ct.z, qv.z, dot);
        dot = fmaf(ct.w, qv.w, dot);
    }

    #pragma unroll
    for (int off = 16; off; off >>= 1)
        dot += __shfl_xor_sync(0xffffffffu, dot, off);

    if (lane == 0) {
        float e = be[r];
        #pragma unroll
        for (int p = 0; p < 8; p++) e += g_ep[p][br];
        float nt = fmaf(ft, n_prev[br], it * expf(e));
        out_n[br] = nt;
        out_h[br] = ot * dot / nt;
    }
}

// ----------------------------------------------------------------------------
extern "C" void kernel_launch(void* const* d_in, const int* in_sizes, int n_in,
                              void* d_out, int out_size)
{
    const float* x      = (const float*)d_in[0];
    const float* h_prev = (const float*)d_in[1];
    const float* C_prev = (const float*)d_in[2];
    const float* n_prev = (const float*)d_in[3];
    const float* Wi = (const float*)d_in[4];
    const float* bi = (const float*)d_in[5];
    const float* Wf = (const float*)d_in[6];
    const float* bf = (const float*)d_in[7];
    const float* Wo = (const float*)d_in[8];
    const float* bo = (const float*)d_in[9];
    const float* Wk = (const float*)d_in[10];
    const float* bk = (const float*)d_in[11];
    const float* Wv = (const float*)d_in[12];
    const float* bv = (const float*)d_in[13];
    const float* Wq = (const float*)d_in[14];
    const float* bq = (const float*)d_in[15];
    const float* We = (const float*)d_in[16];
    const float* be = (const float*)d_in[17];

    float* out_h = (float*)d_out;                          // [64, 1024]
    float* out_C = out_h + B_ * H_;                        // [64, 1024, 1024]
    float* out_n = out_C + (size_t)B_ * H_ * H_;           // [64, 1024]

    gemm9_kernel<<<dim3(16, 9), 256>>>(x, h_prev, Wi, Wf, Wo, Wk, Wv, Wq);
    egemm_kernel<<<dim3(16, 8), 256>>>(We, bk);
    update_kernel<<<dim3(128, 64), 256>>>(C_prev, n_prev, bi, bf, bo, bk, bv, bq, be,
                                          out_h, out_C, out_n);
}

// round 2
// speedup vs baseline: 1.1088x; 1.1088x over previous
#include <cuda_runtime.h>
#include <math.h>

#define B_ 64
#define H_ 1024

// Scratch (allocation-free rule: __device__ globals)
__device__ float g_s[9][B_ * H_];   // raw pre-activations of the 9 K=1024 GEMMs
__device__ float g_ep[8][B_ * H_];  // split-K partials of e = k_t @ We

// ----------------------------------------------------------------------------
// Kernel 1: nine K=1024 GEMMs, M=64, N=1024. TN=64 -> 16 n-tiles x 9 = 144 blocks
// Double-buffered smem pipeline: LDG(next) -> compute(cur) -> STS(next) -> sync
// ----------------------------------------------------------------------------
__global__ __launch_bounds__(256, 1) void gemm9_kernel(
    const float* __restrict__ x, const float* __restrict__ h,
    const float* __restrict__ Wi, const float* __restrict__ Wf,
    const float* __restrict__ Wo, const float* __restrict__ Wk,
    const float* __restrict__ Wv, const float* __restrict__ Wq)
{
    constexpr int TK = 32;
    __shared__ __align__(16) float As[2][TK][64 + 4];
    __shared__ __align__(16) float Ws[2][TK][64 + 4];

    const int mat = blockIdx.y;
    const float* A;
    const float* W;
    switch (mat) {
        case 0: A = x; W = Wi;             break;
        case 1: A = h; W = Wi + H_ * H_;   break;
        case 2: A = x; W = Wf;             break;
        case 3: A = h; W = Wf + H_ * H_;   break;
        case 4: A = x; W = Wo;             break;
        case 5: A = h; W = Wo + H_ * H_;   break;
        case 6: A = x; W = Wk;             break;
        case 7: A = x; W = Wv;             break;
        default: A = h; W = Wq;            break;
    }
    float* out = g_s[mat];

    const int n0 = blockIdx.x * 64;
    const int t  = threadIdx.x;
    const int tr = t >> 4;       // 0..15 -> rows tr*4..tr*4+3
    const int tc = t & 15;       // 0..15 -> cols tc*4..tc*4+3

    // load-thread mapping
    const int arow = t >> 3;            // 0..31 (and +32)
    const int akq  = (t & 7) << 2;      // 0,4,..28
    const int wr   = t >> 4;            // 0..15 (and +16)
    const int wc   = (t & 15) << 2;     // 0,4,..60

    float acc[4][4] = {};
    float4 pa0, pa1, pw0, pw1;

    // prologue: tile 0 -> buffer 0
    pa0 = *(const float4*)(A + arow * H_ + akq);
    pa1 = *(const float4*)(A + (arow + 32) * H_ + akq);
    pw0 = *(const float4*)(W + (size_t)wr * H_ + n0 + wc);
    pw1 = *(const float4*)(W + (size_t)(wr + 16) * H_ + n0 + wc);
    As[0][akq + 0][arow] = pa0.x;  As[0][akq + 1][arow] = pa0.y;
    As[0][akq + 2][arow] = pa0.z;  As[0][akq + 3][arow] = pa0.w;
    As[0][akq + 0][arow + 32] = pa1.x;  As[0][akq + 1][arow + 32] = pa1.y;
    As[0][akq + 2][arow + 32] = pa1.z;  As[0][akq + 3][arow + 32] = pa1.w;
    *(float4*)&Ws[0][wr][wc]      = pw0;
    *(float4*)&Ws[0][wr + 16][wc] = pw1;
    __syncthreads();

    constexpr int NT = H_ / TK;  // 32 tiles
    #pragma unroll 1
    for (int tile = 0; tile < NT; tile++) {
        const int cur = tile & 1;
        const int nxt = cur ^ 1;

        if (tile + 1 < NT) {
            const int k0n = (tile + 1) * TK;
            pa0 = *(const float4*)(A + arow * H_ + k0n + akq);
            pa1 = *(const float4*)(A + (arow + 32) * H_ + k0n + akq);
            pw0 = *(const float4*)(W + (size_t)(k0n + wr) * H_ + n0 + wc);
            pw1 = *(const float4*)(W + (size_t)(k0n + wr + 16) * H_ + n0 + wc);
        }

        #pragma unroll
        for (int kk = 0; kk < TK; kk++) {
            float4 a = *(const float4*)&As[cur][kk][tr << 2];
            float4 b = *(const float4*)&Ws[cur][kk][tc << 2];
            acc[0][0] = fmaf(a.x, b.x, acc[0][0]);
            acc[0][1] = fmaf(a.x, b.y, acc[0][1]);
            acc[0][2] = fmaf(a.x, b.z, acc[0][2]);
            acc[0][3] = fmaf(a.x, b.w, acc[0][3]);
            acc[1][0] = fmaf(a.y, b.x, acc[1][0]);
            acc[1][1] = fmaf(a.y, b.y, acc[1][1]);
            acc[1][2] = fmaf(a.y, b.z, acc[1][2]);
            acc[1][3] = fmaf(a.y, b.w, acc[1][3]);
            acc[2][0] = fmaf(a.z, b.x, acc[2][0]);
            acc[2][1] = fmaf(a.z, b.y, acc[2][1]);
            acc[2][2] = fmaf(a.z, b.z, acc[2][2]);
            acc[2][3] = fmaf(a.z, b.w, acc[2][3]);
            acc[3][0] = fmaf(a.w, b.x, acc[3][0]);
            acc[3][1] = fmaf(a.w, b.y, acc[3][1]);
            acc[3][2] = fmaf(a.w, b.z, acc[3][2]);
            acc[3][3] = fmaf(a.w, b.w, acc[3][3]);
        }

        if (tile + 1 < NT) {
            As[nxt][akq + 0][arow] = pa0.x;  As[nxt][akq + 1][arow] = pa0.y;
            As[nxt][akq + 2][arow] = pa0.z;  As[nxt][akq + 3][arow] = pa0.w;
            As[nxt][akq + 0][arow + 32] = pa1.x;  As[nxt][akq + 1][arow + 32] = pa1.y;
            As[nxt][akq + 2][arow + 32] = pa1.z;  As[nxt][akq + 3][arow + 32] = pa1.w;
            *(float4*)&Ws[nxt][wr][wc]      = pw0;
            *(float4*)&Ws[nxt][wr + 16][wc] = pw1;
        }
        __syncthreads();
    }

    #pragma unroll
    for (int i = 0; i < 4; i++) {
        int row = (tr << 2) + i;
        float4 v = make_float4(acc[i][0], acc[i][1], acc[i][2], acc[i][3]);
        *(float4*)(out + row * H_ + n0 + (tc << 2)) = v;
    }
}

// ----------------------------------------------------------------------------
// Kernel 2: e partials. A = (g_s[6] + bk) [64,1024], W = We. split-K=8.
// grid (16 n-tiles, 8 k-chunks of 128). Double-buffered like gemm9.
// ----------------------------------------------------------------------------
__global__ __launch_bounds__(256, 1) void egemm_kernel(
    const float* __restrict__ We, const float* __restrict__ bk)
{
    constexpr int TK = 32;
    __shared__ __align__(16) float As[2][TK][64 + 4];
    __shared__ __align__(16) float Ws[2][TK][64 + 4];

    const float* A = &g_s[6][0];
    float* out = &g_ep[blockIdx.y][0];
    const int kbase = blockIdx.y * 128;
    const int n0 = blockIdx.x * 64;
    const int t  = threadIdx.x;
    const int tr = t >> 4;
    const int tc = t & 15;

    const int arow = t >> 3;
    const int akq  = (t & 7) << 2;
    const int wr   = t >> 4;
    const int wc   = (t & 15) << 2;

    float acc[4][4] = {};
    float4 pa0, pa1, pw0, pw1, pb;

    // prologue: tile 0
    pa0 = *(const float4*)(A + arow * H_ + kbase + akq);
    pa1 = *(const float4*)(A + (arow + 32) * H_ + kbase + akq);
    pb  = *(const float4*)(bk + kbase + akq);
    pw0 = *(const float4*)(We + (size_t)(kbase + wr) * H_ + n0 + wc);
    pw1 = *(const float4*)(We + (size_t)(kbase + wr + 16) * H_ + n0 + wc);
    As[0][akq + 0][arow] = pa0.x + pb.x;  As[0][akq + 1][arow] = pa0.y + pb.y;
    As[0][akq + 2][arow] = pa0.z + pb.z;  As[0][akq + 3][arow] = pa0.w + pb.w;
    As[0][akq + 0][arow + 32] = pa1.x + pb.x;  As[0][akq + 1][arow + 32] = pa1.y + pb.y;
    As[0][akq + 2][arow + 32] = pa1.z + pb.z;  As[0][akq + 3][arow + 32] = pa1.w + pb.w;
    *(float4*)&Ws[0][wr][wc]      = pw0;
    *(float4*)&Ws[0][wr + 16][wc] = pw1;
    __syncthreads();

    #pragma unroll 1
    for (int tile = 0; tile < 4; tile++) {
        const int cur = tile & 1;
        const int nxt = cur ^ 1;

        if (tile + 1 < 4) {
            const int k0n = kbase + (tile + 1) * TK;
            pa0 = *(const float4*)(A + arow * H_ + k0n + akq);
            pa1 = *(const float4*)(A + (arow + 32) * H_ + k0n + akq);
            pb  = *(const float4*)(bk + k0n + akq);
            pw0 = *(const float4*)(We + (size_t)(k0n + wr) * H_ + n0 + wc);
            pw1 = *(const float4*)(We + (size_t)(k0n + wr + 16) * H_ + n0 + wc);
        }

        #pragma unroll
        for (int kk = 0; kk < TK; kk++) {
            float4 a = *(const float4*)&As[cur][kk][tr << 2];
            float4 b = *(const float4*)&Ws[cur][kk][tc << 2];
            #pragma unroll
            for (int i = 0; i < 4; i++) {
                float av = (i == 0) ? a.x : (i == 1) ? a.y : (i == 2) ? a.z : a.w;
                acc[i][0] = fmaf(av, b.x, acc[i][0]);
                acc[i][1] = fmaf(av, b.y, acc[i][1]);
                acc[i][2] = fmaf(av, b.z, acc[i][2]);
                acc[i][3] = fmaf(av, b.w, acc[i][3]);
            }
        }

        if (tile + 1 < 4) {
            As[nxt][akq + 0][arow] = pa0.x + pb.x;  As[nxt][akq + 1][arow] = pa0.y + pb.y;
            As[nxt][akq + 2][arow] = pa0.z + pb.z;  As[nxt][akq + 3][arow] = pa0.w + pb.w;
            As[nxt][akq + 0][arow + 32] = pa1.x + pb.x;  As[nxt][akq + 1][arow + 32] = pa1.y + pb.y;
            As[nxt][akq + 2][arow + 32] = pa1.z + pb.z;  As[nxt][akq + 3][arow + 32] = pa1.w + pb.w;
            *(float4*)&Ws[nxt][wr][wc]      = pw0;
            *(float4*)&Ws[nxt][wr + 16][wc] = pw1;
        }
        __syncthreads();
    }

    #pragma unroll
    for (int i = 0; i < 4; i++) {
        int row = (tr << 2) + i;
        float4 v = make_float4(acc[i][0], acc[i][1], acc[i][2], acc[i][3]);
        *(float4*)(out + row * H_ + n0 + (tc << 2)) = v;
    }
}

// ----------------------------------------------------------------------------
// Kernel 3: the roofline pass. Streams C_prev -> C_t once (with streaming cache
// hints), fused with gates, h numerator dot, n_t, h_t. One warp per C row.
// ----------------------------------------------------------------------------
__device__ __forceinline__ float sigmoidf_(float z) {
    return 1.0f / (1.0f + expf(-z));
}

__global__ __launch_bounds__(256, 8) void update_kernel(
    const float* __restrict__ C_prev, const float* __restrict__ n_prev,
    const float* __restrict__ bi, const float* __restrict__ bf,
    const float* __restrict__ bo, const float* __restrict__ bk,
    const float* __restrict__ bv, const float* __restrict__ bq,
    const float* __restrict__ be,
    float* __restrict__ out_h, float* __restrict__ out_C,
    float* __restrict__ out_n)
{
    __shared__ __align__(16) float ks[H_];
    __shared__ __align__(16) float qs[H_];

    const int b    = blockIdx.y;
    const int r0   = blockIdx.x * 8;
    const int t    = threadIdx.x;
    const int w    = t >> 5;
    const int lane = t & 31;

    // k_t[b,:] and q_t[b,:] into smem (256 threads * float4 = 1024)
    {
        int c = t << 2;
        float4 kvv = *(const float4*)(&g_s[6][b * H_] + c);
        float4 bkv = *(const float4*)(bk + c);
        float4 qvv = *(const float4*)(&g_s[8][b * H_] + c);
        float4 bqv = *(const float4*)(bq + c);
        *(float4*)&ks[c] = make_float4(kvv.x + bkv.x, kvv.y + bkv.y,
                                       kvv.z + bkv.z, kvv.w + bkv.w);
        *(float4*)&qs[c] = make_float4(qvv.x + bqv.x, qvv.y + bqv.y,
                                       qvv.z + bqv.z, qvv.w + bqv.w);
    }
    __syncthreads();

    const int r = r0 + w;
    const int br = b * H_ + r;

    const float it = sigmoidf_(g_s[0][br] + g_s[1][br] + bi[r]);
    const float ft = sigmoidf_(g_s[2][br] + g_s[3][br] + bf[r]);
    const float ot = sigmoidf_(g_s[4][br] + g_s[5][br] + bo[r]);
    const float vt = g_s[7][br] + bv[r];
    const float iv = it * vt;

    const size_t base = (size_t)b * H_ * H_ + (size_t)r * H_;
    float dot = 0.0f;

    #pragma unroll
    for (int it8 = 0; it8 < 8; it8++) {
        int c = (lane << 2) + (it8 << 7);
        float4 cp = __ldcs((const float4*)(C_prev + base + c));
        float4 kv = *(const float4*)&ks[c];
        float4 qv = *(const float4*)&qs[c];
        float4 ct;
        ct.x = fmaf(ft, cp.x, iv * kv.x);
        ct.y = fmaf(ft, cp.y, iv * kv.y);
        ct.z = fmaf(ft, cp.z, iv * kv.z);
        ct.w = fmaf(ft, cp.w, iv * kv.w);
        __stcs((float4*)(out_C + base + c), ct);
        dot = fmaf(ct.x, qv.x, dot);
        dot = fmaf(ct.y, qv.y, dot);
        dot = fmaf(ct.z, qv.z, dot);
        dot = fmaf(ct.w, qv.w, dot);
    }

    #pragma unroll
    for (int off = 16; off; off >>= 1)
        dot += __shfl_xor_sync(0xffffffffu, dot, off);

    if (lane == 0) {
        float e = be[r];
        #pragma unroll
        for (int p = 0; p < 8; p++) e += g_ep[p][br];
        float nt = fmaf(ft, n_prev[br], it * expf(e));
        out_n[br] = nt;
        out_h[br] = ot * dot / nt;
    }
}

// ----------------------------------------------------------------------------
extern "C" void kernel_launch(void* const* d_in, const int* in_sizes, int n_in,
                              void* d_out, int out_size)
{
    const float* x      = (const float*)d_in[0];
    const float* h_prev = (const float*)d_in[1];
    const float* C_prev = (const float*)d_in[2];
    const float* n_prev = (const float*)d_in[3];
    const float* Wi = (const float*)d_in[4];
    const float* bi = (const float*)d_in[5];
    const float* Wf = (const float*)d_in[6];
    const float* bf = (const float*)d_in[7];
    const float* Wo = (const float*)d_in[8];
    const float* bo = (const float*)d_in[9];
    const float* Wk = (const float*)d_in[10];
    const float* bk = (const float*)d_in[11];
    const float* Wv = (const float*)d_in[12];
    const float* bv = (const float*)d_in[13];
    const float* Wq = (const float*)d_in[14];
    const float* bq = (const float*)d_in[15];
    const float* We = (const float*)d_in[16];
    const float* be = (const float*)d_in[17];

    float* out_h = (float*)d_out;                          // [64, 1024]
    float* out_C = out_h + B_ * H_;                        // [64, 1024, 1024]
    float* out_n = out_C + (size_t)B_ * H_ * H_;           // [64, 1024]

    gemm9_kernel<<<dim3(16, 9), 256>>>(x, h_prev, Wi, Wf, Wo, Wk, Wv, Wq);
    egemm_kernel<<<dim3(16, 8), 256>>>(We, bk);
    update_kernel<<<dim3(128, 64), 256>>>(C_prev, n_prev, bi, bf, bo, bk, bv, bq, be,
                                          out_h, out_C, out_n);
}